// round 4
// baseline (speedup 1.0000x reference)
#include <cuda_runtime.h>
#include <math.h>
#include <stdint.h>

#ifndef M_PI
#define M_PI 3.14159265358979323846
#endif

// Problem dims
#define S_LEN 128
#define B_SZ  128
#define E_DIM 64
#define H_DIM 8
#define NQ_   8
#define T_OUT 12
#define NSAMP (S_LEN * B_SZ)   // 16384
#define N_OPS 30

// ---------------------------------------------------------------------------
// Scratch (device globals; no allocation allowed)
// ---------------------------------------------------------------------------
__device__ float g_zx[NSAMP * 32];   // [s*B+b][g*8+q] : x-part of z (+b_in+phi)
__device__ float g_h [NSAMP * 8];    // [s*B+b][h]     : LSTM hidden outputs

// Random-layer op list (host-generated each call, passed by value)
struct QOps {
    int   kind[N_OPS];   // 0=rx, 1=ry, 2=rz, 3=cnot
    int   wa[N_OPS];     // wire (rot) / control (cnot)
    int   wb[N_OPS];     // target (cnot)
    float c[N_OPS];      // cos(theta/2)
    float s[N_OPS];      // sin(theta/2)
};

// ---------------------------------------------------------------------------
// Kernel 1: embedding gather + input projection
// zx[sb][l] = b_in[l] + phi[l] + sum_e emb[tok[sb]][e] * Win[l][e]   (l = g*8+q)
// ---------------------------------------------------------------------------
__global__ void k_embed(const float* __restrict__ emb,
                        const float* __restrict__ Win,
                        const float* __restrict__ b_in,
                        const float* __restrict__ phi,
                        const void*  __restrict__ sent_raw)
{
    __shared__ float winT[64 * 32];  // [e][l], transposed for conflict-free LDS
    __shared__ float bp[32];

    int tid = threadIdx.x;  // 256 threads
    for (int k = tid; k < 64 * 32; k += 256) {
        int e = k >> 5, l = k & 31;
        winT[k] = Win[l * 72 + e];
    }
    if (tid < 32) bp[tid] = b_in[tid] + phi[tid];
    __syncthreads();

    // dtype sniff: if sentence is int64, the high 32-bit words of the first
    // elements are all zero (tokens < 30000). Probability of a false positive
    // with int32 data is (1/30000)^16 ~ 0.
    const int* si = (const int*)sent_raw;
    bool is64 = true;
    #pragma unroll
    for (int k = 0; k < 16; k++)
        if (si[2 * k + 1] != 0) is64 = false;

    int wid = tid >> 5, l = tid & 31;
    int sb = blockIdx.x * 8 + wid;   // s*B + b

    long long tok = is64 ? ((const long long*)sent_raw)[sb] : (long long)si[sb];
    const float* er = emb + (long long)tok * 64;

    float acc = bp[l];
    #pragma unroll
    for (int e = 0; e < 64; e++)
        acc = fmaf(er[e], winT[e * 32 + l], acc);   // er[e] is a warp broadcast

    g_zx[sb * 32 + l] = acc;
}

// ---------------------------------------------------------------------------
// Kernel 2: LSTM recurrence. One warp per batch element b.
// lane l: (g = l>>3, q/h = l&7). All state in registers + shfl.
// ---------------------------------------------------------------------------
__global__ void k_lstm(const float* __restrict__ Win,
                       const float* __restrict__ Wout,
                       const float* __restrict__ b_out)
{
    const unsigned FULL = 0xffffffffu;
    int b = blockIdx.x;
    int l = threadIdx.x;
    int g = l >> 3, q = l & 7, h = l & 7;

    float winh[8], wo[8];
    #pragma unroll
    for (int j = 0; j < 8; j++) {
        winh[j] = Win[l * 72 + 64 + j];            // h-part of Win row l
        wo[j]   = Wout[(g * 8 + h) * 8 + j];       // Wout[g][h][j]
    }
    float bo = b_out[g * 8 + h];

    float cst = 0.f, hh = 0.f;
    for (int s = 0; s < S_LEN; s++) {
        float z = g_zx[(s * B_SZ + b) * 32 + l];
        #pragma unroll
        for (int j = 0; j < 8; j++)
            z = fmaf(__shfl_sync(FULL, hh, j), winh[j], z);

        float p = cosf(z);
        // inclusive prefix product over q within each gate group of 8 lanes
        #pragma unroll
        for (int d = 1; d < 8; d <<= 1) {
            float t = __shfl_up_sync(FULL, p, d, 8);
            if (q >= d) p *= t;
        }

        float pre = bo;   // pre[g][h] on lane g*8+h
        #pragma unroll
        for (int j = 0; j < 8; j++)
            pre = fmaf(__shfl_sync(FULL, p, (g << 3) | j), wo[j], pre);

        float pf = __shfl_sync(FULL, pre, h);
        float pi = __shfl_sync(FULL, pre, 8  | h);
        float pg = __shfl_sync(FULL, pre, 16 | h);
        float po = __shfl_sync(FULL, pre, 24 | h);

        float fg = 1.f / (1.f + expf(-pf));
        float ig = 1.f / (1.f + expf(-pi));
        float gg = tanhf(pg);
        float og = 1.f / (1.f + expf(-po));

        cst = fg * cst + ig * gg;      // all lanes with same h compute identical c/h
        hh  = og * tanhf(cst);

        if (l < 8) g_h[(s * B_SZ + b) * 8 + l] = hh;
    }
}

// ---------------------------------------------------------------------------
// Kernel 3: QFC head. One warp per sample r (r = b*S + s).
// 8-qubit statevector (256 complex amps) in shared memory per warp.
// Wire w lives on bit position (7-w) of the flattened index.
// ---------------------------------------------------------------------------
__global__ void k_qfc(const float* __restrict__ phiq,
                      const float* __restrict__ Whead,
                      const float* __restrict__ b_head,
                      float* __restrict__ out,
                      QOps ops)
{
    const unsigned FULL = 0xffffffffu;
    __shared__ float2 amp_s[8][256];

    int tid = threadIdx.x, wid = tid >> 5, l = tid & 31;
    float2* amp = amp_s[wid];

    int r = blockIdx.x * 8 + wid;
    int s = r & 127, b = r >> 7;        // flat row r -> (b, s); b = r // S, s = r % S

    const float* th = &g_h[(s * B_SZ + b) * 8];
    float cw[8], sw[8];
    #pragma unroll
    for (int w = 0; w < 8; w++) {
        float t = 0.5f * th[w];
        cw[w] = cosf(t); sw[w] = sinf(t);
    }

    // Product-state init replaces the 8 data-dependent RY gates (RY is real).
    #pragma unroll
    for (int k = 0; k < 8; k++) {
        int i = k * 32 + l;
        float a = 1.f;
        #pragma unroll
        for (int w = 0; w < 8; w++)
            a *= ((i >> (7 - w)) & 1) ? sw[w] : cw[w];
        amp[i] = make_float2(a, 0.f);
    }
    __syncwarp();

    // 30 fixed random ops (uniform control flow across the warp)
    for (int op = 0; op < N_OPS; op++) {
        int kind = ops.kind[op];
        if (kind == 3) {
            // CNOT: swap amps (control bit = 1) across target bit
            int pc = 7 - ops.wa[op], pt = 7 - ops.wb[op];
            int plo = pc < pt ? pc : pt;
            int phi_ = pc < pt ? pt : pc;
            #pragma unroll
            for (int k = 0; k < 2; k++) {
                int j  = k * 32 + l;                                   // 64 swap pairs
                int t1 = ((j  >> plo ) << (plo  + 1)) | (j  & ((1 << plo ) - 1));
                int i0 = ((t1 >> phi_) << (phi_ + 1)) | (t1 & ((1 << phi_) - 1));
                int ia = i0 | (1 << pc);
                int ib = ia | (1 << pt);
                float2 x = amp[ia], y = amp[ib];
                amp[ia] = y; amp[ib] = x;
            }
        } else {
            int p = 7 - ops.wa[op];
            float c = ops.c[op], sn = ops.s[op];
            #pragma unroll
            for (int k = 0; k < 4; k++) {
                int j  = k * 32 + l;                                   // 128 pairs
                int i0 = ((j >> p) << (p + 1)) | (j & ((1 << p) - 1));
                int i1 = i0 | (1 << p);
                float2 a0 = amp[i0], a1 = amp[i1];
                float2 n0, n1;
                if (kind == 0) {        // RX
                    n0 = make_float2(c * a0.x + sn * a1.y, c * a0.y - sn * a1.x);
                    n1 = make_float2(c * a1.x + sn * a0.y, c * a1.y - sn * a0.x);
                } else if (kind == 1) { // RY (real)
                    n0 = make_float2(c * a0.x - sn * a1.x, c * a0.y - sn * a1.y);
                    n1 = make_float2(sn * a0.x + c * a1.x, sn * a0.y + c * a1.y);
                } else {                // RZ: diag(e^{-i t}, e^{+i t})
                    n0 = make_float2(c * a0.x + sn * a0.y, c * a0.y - sn * a0.x);
                    n1 = make_float2(c * a1.x - sn * a1.y, c * a1.y + sn * a1.x);
                }
                amp[i0] = n0; amp[i1] = n1;
            }
        }
        __syncwarp();
    }

    // Final trainable RX(phiq[w]) on every wire
    #pragma unroll
    for (int w = 0; w < 8; w++) {
        float t = 0.5f * phiq[w];
        float c = cosf(t), sn = sinf(t);
        int p = 7 - w;
        #pragma unroll
        for (int k = 0; k < 4; k++) {
            int j  = k * 32 + l;
            int i0 = ((j >> p) << (p + 1)) | (j & ((1 << p) - 1));
            int i1 = i0 | (1 << p);
            float2 a0 = amp[i0], a1 = amp[i1];
            amp[i0] = make_float2(c * a0.x + sn * a1.y, c * a0.y - sn * a1.x);
            amp[i1] = make_float2(c * a1.x + sn * a0.y, c * a1.y - sn * a0.x);
        }
        __syncwarp();
    }

    // Measure <Z_w> for all wires
    float z[8];
    #pragma unroll
    for (int w = 0; w < 8; w++) z[w] = 0.f;
    #pragma unroll
    for (int k = 0; k < 8; k++) {
        int i = k * 32 + l;
        float2 a = amp[i];
        float pb = a.x * a.x + a.y * a.y;
        #pragma unroll
        for (int w = 0; w < 8; w++)
            z[w] += ((i >> (7 - w)) & 1) ? -pb : pb;
    }
    #pragma unroll
    for (int off = 16; off >= 1; off >>= 1) {
        #pragma unroll
        for (int w = 0; w < 8; w++)
            z[w] += __shfl_xor_sync(FULL, z[w], off);
    }

    // Head + log_softmax over 12 classes (lanes 0..11)
    float lg = -INFINITY;
    if (l < T_OUT) {
        lg = b_head[l];
        #pragma unroll
        for (int w = 0; w < 8; w++)
            lg = fmaf(Whead[l * 8 + w], z[w], lg);
    }
    float m = lg;
    #pragma unroll
    for (int off = 16; off >= 1; off >>= 1)
        m = fmaxf(m, __shfl_xor_sync(FULL, m, off));
    float e = (l < T_OUT) ? expf(lg - m) : 0.f;
    float se = e;
    #pragma unroll
    for (int off = 16; off >= 1; off >>= 1)
        se += __shfl_xor_sync(FULL, se, off);

    if (l < T_OUT)
        out[r * T_OUT + l] = lg - m - logf(se);
}

// ---------------------------------------------------------------------------
// Host: numpy-legacy MT19937 (RandomState(1234)) to rebuild _RAND_OPS
// ---------------------------------------------------------------------------
namespace {

struct MT19937 {
    uint32_t mt[624];
    int mti;
    void seed(uint32_t s) {
        mt[0] = s;
        for (int i = 1; i < 624; i++)
            mt[i] = 1812433253u * (mt[i - 1] ^ (mt[i - 1] >> 30)) + (uint32_t)i;
        mti = 624;
    }
    uint32_t next() {
        if (mti >= 624) {
            for (int k = 0; k < 624; k++) {
                uint32_t y = (mt[k] & 0x80000000u) | (mt[(k + 1) % 624] & 0x7fffffffu);
                mt[k] = mt[(k + 397) % 624] ^ (y >> 1) ^ ((y & 1u) ? 0x9908b0dfu : 0u);
            }
            mti = 0;
        }
        uint32_t y = mt[mti++];
        y ^= y >> 11;
        y ^= (y << 7)  & 0x9d2c5680u;
        y ^= (y << 15) & 0xefc60000u;
        y ^= y >> 18;
        return y;
    }
    // numpy legacy randint(0, n): masked rejection, 32-bit draws (rng <= 2^32-1)
    uint32_t randint(uint32_t n) {
        uint32_t mx = n - 1;
        if (mx == 0) return 0;
        uint32_t mask = mx;
        mask |= mask >> 1; mask |= mask >> 2; mask |= mask >> 4;
        mask |= mask >> 8; mask |= mask >> 16;
        uint32_t v;
        do { v = next() & mask; } while (v > mx);
        return v;
    }
    double rdouble() {   // rk_double
        uint32_t a = next() >> 5, b2 = next() >> 6;
        return (a * 67108864.0 + b2) / 9007199254740992.0;
    }
};

void build_ops(QOps& o) {
    MT19937 mt;
    mt.seed(1234u);
    for (int n = 0; n < N_OPS; n++) {
        uint32_t kind = mt.randint(4);
        if (kind == 3) {   // H=8 wires >= 2 always
            int c = (int)mt.randint(8);
            int t = (int)mt.randint(7);
            if (t >= c) t++;
            o.kind[n] = 3; o.wa[n] = c; o.wb[n] = t;
            o.c[n] = 0.f;  o.s[n] = 0.f;
        } else {
            int w = (int)mt.randint(8);
            double ang = mt.rdouble() * (2.0 * M_PI);
            float angf = (float)ang;           // reference casts angle to f32
            o.kind[n] = (int)(kind % 3);       // 0=rx,1=ry,2=rz
            o.wa[n] = w; o.wb[n] = 0;
            o.c[n] = cosf(angf * 0.5f);
            o.s[n] = sinf(angf * 0.5f);
        }
    }
}

} // namespace

// ---------------------------------------------------------------------------
extern "C" void kernel_launch(void* const* d_in, const int* in_sizes, int n_in,
                              void* d_out, int out_size)
{
    const float* emb    = (const float*)d_in[0];
    const float* Win    = (const float*)d_in[1];
    const float* b_in   = (const float*)d_in[2];
    const float* phi    = (const float*)d_in[3];
    const float* Wout   = (const float*)d_in[4];
    const float* b_out  = (const float*)d_in[5];
    const float* phiq   = (const float*)d_in[6];
    const float* Whead  = (const float*)d_in[7];
    const float* b_head = (const float*)d_in[8];
    const void*  sent   = (const void*)d_in[9];

    QOps ops;
    build_ops(ops);   // deterministic, recomputed every call

    k_embed<<<NSAMP / 8, 256>>>(emb, Win, b_in, phi, sent);
    k_lstm <<<B_SZ, 32>>>(Win, Wout, b_out);
    k_qfc  <<<NSAMP / 8, 256>>>(phiq, Whead, b_head, (float*)d_out, ops);
}

// round 5
// speedup vs baseline: 3.2056x; 3.2056x over previous
#include <cuda_runtime.h>
#include <math.h>
#include <stdint.h>

#ifndef M_PI
#define M_PI 3.14159265358979323846
#endif

// Problem dims
#define S_LEN 128
#define B_SZ  128
#define E_DIM 64
#define H_DIM 8
#define NQ_   8
#define T_OUT 12
#define NSAMP (S_LEN * B_SZ)   // 16384
#define N_OPS 30

// ---------------------------------------------------------------------------
// Scratch (device globals; no allocation allowed)
// ---------------------------------------------------------------------------
__device__ float g_zx[NSAMP * 32];   // [s*B+b][g*8+q] : x-part of z (+b_in+phi)
__device__ float g_h [NSAMP * 8];    // [s*B+b][h]     : LSTM hidden outputs

// Random-layer op list (host-generated each call, passed by value)
struct QOps {
    int   kind[N_OPS];   // 0=rx, 1=ry, 2=rz, 3=cnot
    int   wa[N_OPS];     // wire (rot) / control (cnot)
    int   wb[N_OPS];     // target (cnot)
    float c[N_OPS];      // cos(theta/2)
    float s[N_OPS];      // sin(theta/2)
};

// ---------------------------------------------------------------------------
// Fast transcendentals (err ~1e-6, tolerance 1e-3)
// ---------------------------------------------------------------------------
__device__ __forceinline__ float fast_sigmoid(float x) {
    return __fdividef(1.f, 1.f + __expf(-x));
}
__device__ __forceinline__ float fast_tanh(float x) {
    x = fminf(fmaxf(x, -15.f), 15.f);       // avoid exp overflow -> NaN
    float t = __expf(2.f * x);
    return __fdividef(t - 1.f, t + 1.f);
}

// ---------------------------------------------------------------------------
// Kernel 1: embedding gather + input projection. 4 samples per warp.
// zx[sb][l] = b_in[l] + phi[l] + sum_e emb[tok[sb]][e] * Win[l][e]
// ---------------------------------------------------------------------------
__global__ void __launch_bounds__(256) k_embed(
        const float* __restrict__ emb,
        const float* __restrict__ Win,
        const float* __restrict__ b_in,
        const float* __restrict__ phi,
        const void*  __restrict__ sent_raw)
{
    __shared__ float winT[64 * 32];  // [e][l], transposed for conflict-free LDS
    __shared__ float bp[32];

    int tid = threadIdx.x;  // 256 threads
    for (int k = tid; k < 64 * 32; k += 256) {
        int e = k >> 5, l = k & 31;
        winT[k] = Win[l * 72 + e];
    }
    if (tid < 32) bp[tid] = b_in[tid] + phi[tid];
    __syncthreads();

    // dtype sniff: int64 sentence has all-zero high words (tokens < 30000)
    const int* si = (const int*)sent_raw;
    bool is64 = true;
    #pragma unroll
    for (int k = 0; k < 16; k++)
        if (si[2 * k + 1] != 0) is64 = false;

    int wid = tid >> 5, l = tid & 31;
    int sb0 = blockIdx.x * 32 + wid * 4;   // 4 consecutive samples per warp

    const float* er0; const float* er1; const float* er2; const float* er3;
    {
        long long t0 = is64 ? ((const long long*)sent_raw)[sb0 + 0] : (long long)si[sb0 + 0];
        long long t1 = is64 ? ((const long long*)sent_raw)[sb0 + 1] : (long long)si[sb0 + 1];
        long long t2 = is64 ? ((const long long*)sent_raw)[sb0 + 2] : (long long)si[sb0 + 2];
        long long t3 = is64 ? ((const long long*)sent_raw)[sb0 + 3] : (long long)si[sb0 + 3];
        er0 = emb + t0 * 64; er1 = emb + t1 * 64;
        er2 = emb + t2 * 64; er3 = emb + t3 * 64;
    }

    float a0 = bp[l], a1 = a0, a2 = a0, a3 = a0;
    #pragma unroll
    for (int e = 0; e < 64; e++) {
        float w = winT[e * 32 + l];          // one LDS serves 4 outputs
        a0 = fmaf(er0[e], w, a0);            // er*[e] are warp-broadcast L1 hits
        a1 = fmaf(er1[e], w, a1);
        a2 = fmaf(er2[e], w, a2);
        a3 = fmaf(er3[e], w, a3);
    }
    g_zx[(sb0 + 0) * 32 + l] = a0;
    g_zx[(sb0 + 1) * 32 + l] = a1;
    g_zx[(sb0 + 2) * 32 + l] = a2;
    g_zx[(sb0 + 3) * 32 + l] = a3;
}

// ---------------------------------------------------------------------------
// Kernel 2: LSTM recurrence. One warp per batch element b. Fast intrinsics.
// ---------------------------------------------------------------------------
__global__ void __launch_bounds__(32) k_lstm(
        const float* __restrict__ Win,
        const float* __restrict__ Wout,
        const float* __restrict__ b_out)
{
    const unsigned FULL = 0xffffffffu;
    int b = blockIdx.x;
    int l = threadIdx.x;
    int g = l >> 3, q = l & 7, h = l & 7;

    float winh[8], wo[8];
    #pragma unroll
    for (int j = 0; j < 8; j++) {
        winh[j] = Win[l * 72 + 64 + j];            // h-part of Win row l
        wo[j]   = Wout[(g * 8 + h) * 8 + j];       // Wout[g][h][j]
    }
    float bo = b_out[g * 8 + h];

    float cst = 0.f, hh = 0.f;
    float zbuf = g_zx[b * 32 + l];                 // prefetch s=0
    for (int s = 0; s < S_LEN; s++) {
        float z = zbuf;
        if (s + 1 < S_LEN)
            zbuf = g_zx[((s + 1) * B_SZ + b) * 32 + l];  // hide L2 latency

        #pragma unroll
        for (int j = 0; j < 8; j++)
            z = fmaf(__shfl_sync(FULL, hh, j), winh[j], z);

        float p = __cosf(z);
        // inclusive prefix product over q within each gate group of 8 lanes
        #pragma unroll
        for (int d = 1; d < 8; d <<= 1) {
            float t = __shfl_up_sync(FULL, p, d, 8);
            if (q >= d) p *= t;
        }

        float pre = bo;   // pre[g][h] on lane g*8+h
        #pragma unroll
        for (int j = 0; j < 8; j++)
            pre = fmaf(__shfl_sync(FULL, p, (g << 3) | j), wo[j], pre);

        float pf = __shfl_sync(FULL, pre, h);
        float pi = __shfl_sync(FULL, pre, 8  | h);
        float pg = __shfl_sync(FULL, pre, 16 | h);
        float po = __shfl_sync(FULL, pre, 24 | h);

        float fg = fast_sigmoid(pf);
        float ig = fast_sigmoid(pi);
        float gg = fast_tanh(pg);
        float og = fast_sigmoid(po);

        cst = fmaf(fg, cst, ig * gg);
        hh  = og * fast_tanh(cst);

        if (l < 8) g_h[(s * B_SZ + b) * 8 + l] = hh;
    }
}

// ---------------------------------------------------------------------------
// Kernel 3: QFC head. One warp per sample; statevector fully in REGISTERS.
// Lane l holds amps i = k*32 + l, k = 0..7.
// Index bits 0..4 = lane bits (wires 7..3), bits 5..7 = k bits (wires 2..0).
// ---------------------------------------------------------------------------
#define RXP(i,j) do { float nx0=c*ax[i]+sn*ay[j], ny0=c*ay[i]-sn*ax[j]; \
                      float nx1=c*ax[j]+sn*ay[i], ny1=c*ay[j]-sn*ax[i]; \
                      ax[i]=nx0; ay[i]=ny0; ax[j]=nx1; ay[j]=ny1; } while(0)
#define RYP(i,j) do { float nx0=c*ax[i]-sn*ax[j], ny0=c*ay[i]-sn*ay[j]; \
                      float nx1=sn*ax[i]+c*ax[j], ny1=sn*ay[i]+c*ay[j]; \
                      ax[i]=nx0; ay[i]=ny0; ax[j]=nx1; ay[j]=ny1; } while(0)
#define SWP(i,j) do { float tx=ax[i]; ax[i]=ax[j]; ax[j]=tx; \
                      float ty=ay[i]; ay[i]=ay[j]; ay[j]=ty; } while(0)
#define PAIRS_SWITCH(kb, APPLY) \
    switch (kb) { \
      case 0:  APPLY(0,1); APPLY(2,3); APPLY(4,5); APPLY(6,7); break; \
      case 1:  APPLY(0,2); APPLY(1,3); APPLY(4,6); APPLY(5,7); break; \
      default: APPLY(0,4); APPLY(1,5); APPLY(2,6); APPLY(3,7); break; \
    }

__global__ void __launch_bounds__(256) k_qfc(
        const float* __restrict__ phiq,
        const float* __restrict__ Whead,
        const float* __restrict__ b_head,
        float* __restrict__ out,
        QOps ops)
{
    const unsigned FULL = 0xffffffffu;
    int tid = threadIdx.x, l = tid & 31;
    int r = blockIdx.x * 8 + (tid >> 5);
    int s = r & 127, b = r >> 7;        // flat row r = b*S + s

    const float* th = &g_h[(s * B_SZ + b) * 8];
    float cw[8], sw[8];
    #pragma unroll
    for (int w = 0; w < 8; w++)
        __sincosf(0.5f * th[w], &sw[w], &cw[w]);

    // Product-state init (replaces the 8 data-dependent RY gates; RY is real)
    float base = 1.f;
    #pragma unroll
    for (int w = 3; w < 8; w++)                     // lane-bit wires
        base *= ((l >> (7 - w)) & 1) ? sw[w] : cw[w];

    float ax[8], ay[8];
    #pragma unroll
    for (int k = 0; k < 8; k++) {
        float t = (((k >> 2) & 1) ? sw[0] : cw[0]) *
                  (((k >> 1) & 1) ? sw[1] : cw[1]) *
                  (((k     ) & 1) ? sw[2] : cw[2]);
        ax[k] = base * t;
        ay[k] = 0.f;
    }

    // 30 random ops + 8 trainable RX(phiq) gates — uniform control flow
    for (int op = 0; op < N_OPS + 8; op++) {
        int kind, pa, pb_;
        float c, sn;
        if (op < N_OPS) {
            kind = ops.kind[op];
            pa   = 7 - ops.wa[op];
            pb_  = 7 - ops.wb[op];
            c    = ops.c[op];
            sn   = ops.s[op];
        } else {
            kind = 0;                                 // RX(phiq[w])
            pa   = 7 - (op - N_OPS);
            pb_  = 0;
            __sincosf(0.5f * phiq[op - N_OPS], &sn, &c);
        }

        if (kind == 3) {                              // ---- CNOT ----
            int pc = pa, pt = pb_;
            if (pc < 5 && pt < 5) {                   // both lane bits
                unsigned m = 1u << pt;
                bool ctl = (l >> pc) & 1;
                #pragma unroll
                for (int k = 0; k < 8; k++) {
                    float qx = __shfl_xor_sync(FULL, ax[k], m);
                    float qy = __shfl_xor_sync(FULL, ay[k], m);
                    if (ctl) { ax[k] = qx; ay[k] = qy; }
                }
            } else if (pc < 5) {                      // control lane, target k
                bool ctl = (l >> pc) & 1;
                if (ctl) { PAIRS_SWITCH(pt - 5, SWP); }
            } else if (pt < 5) {                      // control k, target lane
                unsigned m = 1u << pt;
                int ckb = pc - 5;
                #pragma unroll
                for (int k = 0; k < 8; k++) {
                    float qx = __shfl_xor_sync(FULL, ax[k], m);
                    float qy = __shfl_xor_sync(FULL, ay[k], m);
                    if ((k >> ckb) & 1) { ax[k] = qx; ay[k] = qy; }
                }
            } else {                                  // both k bits
                int ckb = pc - 5, tkb = pt - 5;
                switch (ckb * 4 + tkb) {
                  case 1:  SWP(1,3); SWP(5,7); break; // c=b0, t=b1
                  case 2:  SWP(1,5); SWP(3,7); break; // c=b0, t=b2
                  case 4:  SWP(2,3); SWP(6,7); break; // c=b1, t=b0
                  case 6:  SWP(2,6); SWP(3,7); break; // c=b1, t=b2
                  case 8:  SWP(4,5); SWP(6,7); break; // c=b2, t=b0
                  default: SWP(4,6); SWP(5,7); break; // c=b2, t=b1
                }
            }
        } else if (kind == 2) {                       // ---- RZ (diagonal, 0 shfl)
            if (pa < 5) {
                float sg = ((l >> pa) & 1) ? -sn : sn;
                #pragma unroll
                for (int k = 0; k < 8; k++) {
                    float x = ax[k], y = ay[k];
                    ax[k] = c * x + sg * y;
                    ay[k] = c * y - sg * x;
                }
            } else {
                int kb = pa - 5;
                #pragma unroll
                for (int k = 0; k < 8; k++) {
                    float sg = ((k >> kb) & 1) ? -sn : sn;
                    float x = ax[k], y = ay[k];
                    ax[k] = c * x + sg * y;
                    ay[k] = c * y - sg * x;
                }
            }
        } else if (kind == 1) {                       // ---- RY ----
            if (pa < 5) {
                unsigned m = 1u << pa;
                float sg = ((l >> pa) & 1) ? sn : -sn;
                #pragma unroll
                for (int k = 0; k < 8; k++) {
                    float px = __shfl_xor_sync(FULL, ax[k], m);
                    float py = __shfl_xor_sync(FULL, ay[k], m);
                    ax[k] = c * ax[k] + sg * px;
                    ay[k] = c * ay[k] + sg * py;
                }
            } else {
                PAIRS_SWITCH(pa - 5, RYP);
            }
        } else {                                      // ---- RX (lane-symmetric)
            if (pa < 5) {
                unsigned m = 1u << pa;
                #pragma unroll
                for (int k = 0; k < 8; k++) {
                    float px = __shfl_xor_sync(FULL, ax[k], m);
                    float py = __shfl_xor_sync(FULL, ay[k], m);
                    ax[k] = c * ax[k] + sn * py;
                    ay[k] = c * ay[k] - sn * px;
                }
            } else {
                PAIRS_SWITCH(pa - 5, RXP);
            }
        }
    }

    // Measure <Z_w>
    float pb[8];
    #pragma unroll
    for (int k = 0; k < 8; k++) pb[k] = ax[k] * ax[k] + ay[k] * ay[k];

    float z[8];
    float P = ((pb[0] + pb[1]) + (pb[2] + pb[3])) + ((pb[4] + pb[5]) + (pb[6] + pb[7]));
    z[0] = (pb[0] + pb[1] + pb[2] + pb[3]) - (pb[4] + pb[5] + pb[6] + pb[7]); // k bit2
    z[1] = (pb[0] + pb[1] + pb[4] + pb[5]) - (pb[2] + pb[3] + pb[6] + pb[7]); // k bit1
    z[2] = (pb[0] + pb[2] + pb[4] + pb[6]) - (pb[1] + pb[3] + pb[5] + pb[7]); // k bit0
    #pragma unroll
    for (int w = 3; w < 8; w++)
        z[w] = ((l >> (7 - w)) & 1) ? -P : P;

    #pragma unroll
    for (int off = 16; off >= 1; off >>= 1) {
        #pragma unroll
        for (int w = 0; w < 8; w++)
            z[w] += __shfl_xor_sync(FULL, z[w], off);
    }

    // Head + log_softmax over 12 classes (lanes 0..11)
    float lg = -INFINITY;
    if (l < T_OUT) {
        lg = b_head[l];
        #pragma unroll
        for (int w = 0; w < 8; w++)
            lg = fmaf(Whead[l * 8 + w], z[w], lg);
    }
    float m = lg;
    #pragma unroll
    for (int off = 16; off >= 1; off >>= 1)
        m = fmaxf(m, __shfl_xor_sync(FULL, m, off));
    float e = (l < T_OUT) ? expf(lg - m) : 0.f;
    float se = e;
    #pragma unroll
    for (int off = 16; off >= 1; off >>= 1)
        se += __shfl_xor_sync(FULL, se, off);

    if (l < T_OUT)
        out[r * T_OUT + l] = lg - m - logf(se);
}

// ---------------------------------------------------------------------------
// Host: numpy-legacy MT19937 (RandomState(1234)) to rebuild _RAND_OPS
// ---------------------------------------------------------------------------
namespace {

struct MT19937 {
    uint32_t mt[624];
    int mti;
    void seed(uint32_t s) {
        mt[0] = s;
        for (int i = 1; i < 624; i++)
            mt[i] = 1812433253u * (mt[i - 1] ^ (mt[i - 1] >> 30)) + (uint32_t)i;
        mti = 624;
    }
    uint32_t next() {
        if (mti >= 624) {
            for (int k = 0; k < 624; k++) {
                uint32_t y = (mt[k] & 0x80000000u) | (mt[(k + 1) % 624] & 0x7fffffffu);
                mt[k] = mt[(k + 397) % 624] ^ (y >> 1) ^ ((y & 1u) ? 0x9908b0dfu : 0u);
            }
            mti = 0;
        }
        uint32_t y = mt[mti++];
        y ^= y >> 11;
        y ^= (y << 7)  & 0x9d2c5680u;
        y ^= (y << 15) & 0xefc60000u;
        y ^= y >> 18;
        return y;
    }
    uint32_t randint(uint32_t n) {   // numpy legacy: masked rejection
        uint32_t mx = n - 1;
        if (mx == 0) return 0;
        uint32_t mask = mx;
        mask |= mask >> 1; mask |= mask >> 2; mask |= mask >> 4;
        mask |= mask >> 8; mask |= mask >> 16;
        uint32_t v;
        do { v = next() & mask; } while (v > mx);
        return v;
    }
    double rdouble() {   // rk_double
        uint32_t a = next() >> 5, b2 = next() >> 6;
        return (a * 67108864.0 + b2) / 9007199254740992.0;
    }
};

void build_ops(QOps& o) {
    MT19937 mt;
    mt.seed(1234u);
    for (int n = 0; n < N_OPS; n++) {
        uint32_t kind = mt.randint(4);
        if (kind == 3) {   // H=8 wires >= 2 always
            int c = (int)mt.randint(8);
            int t = (int)mt.randint(7);
            if (t >= c) t++;
            o.kind[n] = 3; o.wa[n] = c; o.wb[n] = t;
            o.c[n] = 0.f;  o.s[n] = 0.f;
        } else {
            int w = (int)mt.randint(8);
            double ang = mt.rdouble() * (2.0 * M_PI);
            float angf = (float)ang;           // reference casts angle to f32
            o.kind[n] = (int)(kind % 3);       // 0=rx,1=ry,2=rz
            o.wa[n] = w; o.wb[n] = 0;
            o.c[n] = cosf(angf * 0.5f);
            o.s[n] = sinf(angf * 0.5f);
        }
    }
}

} // namespace

// ---------------------------------------------------------------------------
extern "C" void kernel_launch(void* const* d_in, const int* in_sizes, int n_in,
                              void* d_out, int out_size)
{
    const float* emb    = (const float*)d_in[0];
    const float* Win    = (const float*)d_in[1];
    const float* b_in   = (const float*)d_in[2];
    const float* phi    = (const float*)d_in[3];
    const float* Wout   = (const float*)d_in[4];
    const float* b_out  = (const float*)d_in[5];
    const float* phiq   = (const float*)d_in[6];
    const float* Whead  = (const float*)d_in[7];
    const float* b_head = (const float*)d_in[8];
    const void*  sent   = (const void*)d_in[9];

    QOps ops;
    build_ops(ops);   // deterministic, recomputed every call

    k_embed<<<NSAMP / 32, 256>>>(emb, Win, b_in, phi, sent);
    k_lstm <<<B_SZ, 32>>>(Win, Wout, b_out);
    k_qfc  <<<NSAMP / 8, 256>>>(phiq, Whead, b_head, (float*)d_out, ops);
}